// round 9
// baseline (speedup 1.0000x reference)
#include <cuda_runtime.h>
#include <cuda_fp16.h>
#include <cstdint>
#include <math.h>

// Problem constants (B=1, DIM=512, T=8, H=64, W=64)
#define MDIM 512
#define KDIM 512
#define NDIM 32768
#define SQRT_C 22.62741699796952f

// GEMM tiling
#define BM 128
#define BN 128
#define BK 32
#define NITER (KDIM / BK)      // 16
#define STAGES 5
#define AROW_H 40              // A padded row (halves) -> 80B
#define BROW_H 136             // B padded row (halves) -> 272B
#define A_BYTES (BM * AROW_H * 2)      // 10240
#define B_BYTES (BK * BROW_H * 2)      // 8704
#define STAGE_B (A_BYTES + B_BYTES)    // 18944
#define SMEM_TOTAL (STAGES * STAGE_B)  // 94720

// ---------------- scratch ----------------
__device__ __half g_Wf[MDIM * KDIM];      // fused weight, fp16
__device__ __half g_xh[KDIM * NDIM];      // x converted to fp16
__device__ float  g_bias[MDIM];
__device__ float  g_s[NDIM];

// ---------------- helpers ----------------
__device__ __forceinline__ uint32_t smem_u32(const void* p) {
    uint32_t a;
    asm("{ .reg .u64 t; cvta.to.shared.u64 t, %1; cvt.u32.u64 %0, t; }" : "=r"(a) : "l"(p));
    return a;
}
__device__ __forceinline__ void cp_async16(uint32_t dst, const void* src) {
    asm volatile("cp.async.cg.shared.global [%0], [%1], 16;" :: "r"(dst), "l"(src) : "memory");
}
#define LDSM_X4(r0, r1, r2, r3, addr)                                         \
    asm volatile("ldmatrix.sync.aligned.m8n8.x4.shared.b16 {%0,%1,%2,%3}, [%4];" \
        : "=r"(r0), "=r"(r1), "=r"(r2), "=r"(r3) : "r"(addr))
#define LDSM_X4_T(r0, r1, r2, r3, addr)                                       \
    asm volatile("ldmatrix.sync.aligned.m8n8.x4.trans.shared.b16 {%0,%1,%2,%3}, [%4];" \
        : "=r"(r0), "=r"(r1), "=r"(r2), "=r"(r3) : "r"(addr))

__device__ __forceinline__ void mma_f16(float c[4], uint32_t a0, uint32_t a1, uint32_t a2, uint32_t a3,
                                        uint32_t b0, uint32_t b1) {
    asm volatile(
        "mma.sync.aligned.m16n8k16.row.col.f32.f16.f16.f32 "
        "{%0,%1,%2,%3}, {%4,%5,%6,%7}, {%8,%9}, {%0,%1,%2,%3};"
        : "+f"(c[0]), "+f"(c[1]), "+f"(c[2]), "+f"(c[3])
        : "r"(a0), "r"(a1), "r"(a2), "r"(a3), "r"(b0), "r"(b1));
}
__device__ __forceinline__ void sts16_h8(uint32_t addr, const __half2 h[4]) {
    asm volatile("st.shared.v4.b32 [%0], {%1,%2,%3,%4};" :: "r"(addr),
        "r"(*(const uint32_t*)&h[0]), "r"(*(const uint32_t*)&h[1]),
        "r"(*(const uint32_t*)&h[2]), "r"(*(const uint32_t*)&h[3]) : "memory");
}

// ================= kernel 1: merged fw-GEMM + bias + scale =================
// blocks 0..15    : fuse-weights GEMM (inline fp32->fp16 conversion)
// blocks 16..79   : fused bias (warp per output row)
// blocks 80..335  : RMS scale + fp16 conversion of x
__global__ __launch_bounds__(256, 2) void prep_all_kernel(
    const float* __restrict__ x,
    const float* __restrict__ gamma,
    const float* __restrict__ w_qkv,
    const float* __restrict__ b_qkv,
    const float* __restrict__ w_proj,
    const float* __restrict__ b_proj,
    __half* __restrict__ Wf, float* __restrict__ bias,
    float* __restrict__ s, __half* __restrict__ xh)
{
    extern __shared__ char smem[];
    const int tid = threadIdx.x;
    const int bx  = blockIdx.x;

    if (bx < 16) {
        // ---- fuse-weights GEMM: Wf[m][c] = sum_k w_proj[m][k] * (Wv[k][c]*gamma[c]) ----
        const uint32_t sbase = smem_u32(smem);
        const int lane = tid & 31;
        const int wid  = tid >> 5;
        const int wm   = wid >> 2;
        const int wn   = wid & 3;
        const int ty   = lane >> 2;
        const int tx   = lane & 3;
        const int m0   = (bx >> 2) * BM;
        const int n0   = (bx & 3) * BN;

        // A staging: row = tid>>1 (128 rows), 16 k-halves at ks
        const int a_row = tid >> 1;
        const int a_ks  = (tid & 1) * 16;
        // B staging: krow = tid>>3 (32 rows), 16 c at cs
        const int b_kr  = tid >> 3;
        const int b_cs  = (tid & 7) * 16;

        const float* wv = w_qkv + (size_t)1024 * KDIM;
        float c[4][4][4] = {};

        const uint32_t a_lm = (uint32_t)(((wm * 64 + (lane & 15)) * AROW_H + (lane >> 4) * 8) * 2);
        const uint32_t b_lm = (uint32_t)(A_BYTES + (((lane & 15)) * BROW_H + wn * 32 + (lane >> 4) * 8) * 2);

        #pragma unroll 1
        for (int it = 0; it < NITER; ++it) {
            const int k0 = it * BK;
            // load A (w_proj)
            float4 av[4];
            const float* ap = w_proj + (size_t)(m0 + a_row) * KDIM + k0 + a_ks;
            #pragma unroll
            for (int i = 0; i < 4; i++) av[i] = *reinterpret_cast<const float4*>(ap + 4 * i);
            // load B (Wv) + gamma
            float4 bv[4], gv[4];
            const float* bp = wv + (size_t)(k0 + b_kr) * KDIM + n0 + b_cs;
            #pragma unroll
            for (int i = 0; i < 4; i++) {
                bv[i] = *reinterpret_cast<const float4*>(bp + 4 * i);
                gv[i] = *reinterpret_cast<const float4*>(gamma + n0 + b_cs + 4 * i);
            }
            __syncthreads();   // previous iteration's ldmatrix reads complete
            {
                __half2 h[4];
                #pragma unroll
                for (int i = 0; i < 2; i++) {
                    #pragma unroll
                    for (int j = 0; j < 2; j++) {
                        float4 v = av[i * 2 + j];
                        h[j * 2 + 0] = __floats2half2_rn(v.x, v.y);
                        h[j * 2 + 1] = __floats2half2_rn(v.z, v.w);
                    }
                    sts16_h8(sbase + (uint32_t)(a_row * 80 + a_ks * 2 + i * 16), h);
                }
                #pragma unroll
                for (int i = 0; i < 2; i++) {
                    #pragma unroll
                    for (int j = 0; j < 2; j++) {
                        float4 v = bv[i * 2 + j], g = gv[i * 2 + j];
                        h[j * 2 + 0] = __floats2half2_rn(v.x * g.x, v.y * g.y);
                        h[j * 2 + 1] = __floats2half2_rn(v.z * g.z, v.w * g.w);
                    }
                    sts16_h8(sbase + (uint32_t)(A_BYTES + b_kr * 272 + b_cs * 2 + i * 16), h);
                }
            }
            __syncthreads();

            #pragma unroll
            for (int kk = 0; kk < 2; kk++) {
                uint32_t a[4][4];
                #pragma unroll
                for (int mt = 0; mt < 4; mt++)
                    LDSM_X4(a[mt][0], a[mt][1], a[mt][2], a[mt][3],
                            sbase + a_lm + mt * (16 * AROW_H * 2) + kk * 32);
                uint32_t b[4][2];
                #pragma unroll
                for (int ntp = 0; ntp < 2; ntp++)
                    LDSM_X4_T(b[ntp * 2][0], b[ntp * 2][1], b[ntp * 2 + 1][0], b[ntp * 2 + 1][1],
                              sbase + b_lm + kk * (16 * BROW_H * 2) + ntp * 32);
                #pragma unroll
                for (int mt = 0; mt < 4; mt++)
                    #pragma unroll
                    for (int nt = 0; nt < 4; nt++)
                        mma_f16(c[mt][nt], a[mt][0], a[mt][1], a[mt][2], a[mt][3],
                                b[nt][0], b[nt][1]);
            }
        }

        #pragma unroll
        for (int mt = 0; mt < 4; mt++)
            #pragma unroll
            for (int h = 0; h < 2; h++) {
                const int m = m0 + wm * 64 + mt * 16 + ty + h * 8;
                #pragma unroll
                for (int nt = 0; nt < 4; nt++) {
                    const int nc = wn * 32 + nt * 8 + 2 * tx;
                    *reinterpret_cast<__half2*>(Wf + (size_t)m * KDIM + n0 + nc) =
                        __floats2half2_rn(c[mt][nt][h * 2 + 0], c[mt][nt][h * 2 + 1]);
                }
            }
        return;
    }

    if (bx < 80) {
        // ---- fused bias: warp per output row ----
        const int lane = tid & 31;
        const int o    = (bx - 16) * 8 + (tid >> 5);
        const float* wp = w_proj + (size_t)o * KDIM;
        const float* bq = b_qkv + 1024;
        float acc = 0.f;
        #pragma unroll
        for (int i = 0; i < 16; i++) {
            const int k = lane + 32 * i;
            acc = fmaf(wp[k], bq[k], acc);
        }
        #pragma unroll
        for (int off = 16; off > 0; off >>= 1)
            acc += __shfl_xor_sync(0xFFFFFFFFu, acc, off);
        if (lane == 0) bias[o] = acc + b_proj[o];
        return;
    }

    // ---- RMS scale + fp16 conversion, 128 tokens per block ----
    {
        float2* red = reinterpret_cast<float2*>(smem);
        const int nb = bx - 80;
        const int nl = tid & 63;
        const int q  = tid >> 6;
        const int n  = nb * 128 + nl * 2;

        const float2* p = reinterpret_cast<const float2*>(x + (size_t)(q * 128) * NDIM + n);
        __half2* ph = reinterpret_cast<__half2*>(xh + (size_t)(q * 128) * NDIM + n);
        float ax = 0.f, ay = 0.f;
        #pragma unroll 8
        for (int c = 0; c < 128; c++) {
            float2 v = p[(size_t)c * (NDIM / 2)];
            ax = fmaf(v.x, v.x, ax);
            ay = fmaf(v.y, v.y, ay);
            ph[(size_t)c * (NDIM / 2)] = __floats2half2_rn(v.x, v.y);
        }
        red[tid] = make_float2(ax, ay);
        __syncthreads();
        if (tid < 64) {
            float2 a = red[tid], b = red[tid + 64], c2 = red[tid + 128], d = red[tid + 192];
            float tx2 = a.x + b.x + c2.x + d.x;
            float ty2 = a.y + b.y + c2.y + d.y;
            float2 sv;
            sv.x = SQRT_C / fmaxf(sqrtf(tx2), 1e-12f);
            sv.y = SQRT_C / fmaxf(sqrtf(ty2), 1e-12f);
            *reinterpret_cast<float2*>(s + nb * 128 + tid * 2) = sv;
        }
    }
}

// ================= kernel 2: main GEMM (5-stage cp.async, frag preload) =================
// grid (4 m-tiles fastest, 256 n-tiles): the 4 m-passes over an n-slice run
// in the same wave -> xh read once from DRAM, 3x from L2.
__global__ __launch_bounds__(256, 2) void main_gemm_kernel(
    const __half* __restrict__ A,    // Wf [512,512] fp16
    const __half* __restrict__ Bh,   // x_h [512,32768] fp16 (operand + residual)
    const float* __restrict__ s,
    const float* __restrict__ bias,
    float* __restrict__ C)
{
    extern __shared__ char smem[];
    const uint32_t sbase = smem_u32(smem);
    const int tid  = threadIdx.x;
    const int lane = tid & 31;
    const int wid  = tid >> 5;
    const int wm   = wid >> 2;
    const int wn   = wid & 3;
    const int ty   = lane >> 2;
    const int tx   = lane & 3;
    const int m0   = blockIdx.x * BM;      // 4 m-tiles, fastest dim
    const int n0   = blockIdx.y * BN;      // 256 n-tiles

    const int a_row = tid >> 1;
    const int a_sp  = (tid & 1) * 2;
    const int b_row = tid >> 3;
    const int b_sp  = (tid & 7) * 2;
    const __half* a_src = A + (size_t)(m0 + a_row) * KDIM + a_sp * 8;
    const __half* b_src = Bh + (size_t)b_row * NDIM + n0 + b_sp * 8;

    float c[4][4][4] = {};

    auto issue = [&](int ck) {
        const uint32_t ab = sbase + (uint32_t)(ck % STAGES) * STAGE_B;
        const uint32_t bb = ab + A_BYTES;
        const int k0 = ck * BK;
        #pragma unroll
        for (int ss = 0; ss < 2; ss++)
            cp_async16(ab + (uint32_t)(a_row * 80 + (a_sp + ss) * 16), a_src + k0 + ss * 8);
        #pragma unroll
        for (int ss = 0; ss < 2; ss++)
            cp_async16(bb + (uint32_t)(b_row * 272 + (b_sp + ss) * 16),
                       b_src + (size_t)k0 * NDIM + ss * 8);
        asm volatile("cp.async.commit_group;" ::: "memory");
    };

    issue(0); issue(1); issue(2); issue(3);

    const uint32_t a_lm = (uint32_t)(((wm * 64 + (lane & 15)) * AROW_H + (lane >> 4) * 8) * 2);
    const uint32_t b_lm = (uint32_t)(A_BYTES + (((lane & 15)) * BROW_H + wn * 32 + (lane >> 4) * 8) * 2);

    #pragma unroll 1
    for (int it = 0; it < NITER; ++it) {
        if (it + 3 < NITER)      asm volatile("cp.async.wait_group 3;" ::: "memory");
        else if (it + 2 < NITER) asm volatile("cp.async.wait_group 2;" ::: "memory");
        else if (it + 1 < NITER) asm volatile("cp.async.wait_group 1;" ::: "memory");
        else                     asm volatile("cp.async.wait_group 0;" ::: "memory");
        __syncthreads();
        if (it + 4 < NITER) issue(it + 4);

        const uint32_t stb = sbase + (uint32_t)(it % STAGES) * STAGE_B;

        // preload ALL fragments for both kk sub-steps, then stream 32 mma
        uint32_t a[2][4][4];
        uint32_t b[2][4][2];
        #pragma unroll
        for (int kk = 0; kk < 2; kk++) {
            #pragma unroll
            for (int mt = 0; mt < 4; mt++)
                LDSM_X4(a[kk][mt][0], a[kk][mt][1], a[kk][mt][2], a[kk][mt][3],
                        stb + a_lm + mt * (16 * AROW_H * 2) + kk * 32);
            #pragma unroll
            for (int ntp = 0; ntp < 2; ntp++)
                LDSM_X4_T(b[kk][ntp * 2][0], b[kk][ntp * 2][1],
                          b[kk][ntp * 2 + 1][0], b[kk][ntp * 2 + 1][1],
                          stb + b_lm + kk * (16 * BROW_H * 2) + ntp * 32);
        }
        #pragma unroll
        for (int kk = 0; kk < 2; kk++)
            #pragma unroll
            for (int mt = 0; mt < 4; mt++)
                #pragma unroll
                for (int nt = 0; nt < 4; nt++)
                    mma_f16(c[mt][nt], a[kk][mt][0], a[kk][mt][1], a[kk][mt][2], a[kk][mt][3],
                            b[kk][nt][0], b[kk][nt][1]);
    }

    // ---- epilogue: out = D*s[n] + bias[m] + xh[m][n] ----
    #pragma unroll
    for (int mt = 0; mt < 4; mt++) {
        #pragma unroll
        for (int h = 0; h < 2; h++) {
            const int m = m0 + wm * 64 + mt * 16 + ty + h * 8;
            const float bm = bias[m];
            const __half2* xrow = reinterpret_cast<const __half2*>(Bh + (size_t)m * NDIM + n0);
            float* crow = C + (size_t)m * NDIM + n0;
            #pragma unroll
            for (int nt = 0; nt < 4; nt++) {
                const int nc = wn * 32 + nt * 8 + 2 * tx;
                float2 xv = __half22float2(xrow[nc >> 1]);
                float2 sv = *reinterpret_cast<const float2*>(s + n0 + nc);
                float2 ov;
                ov.x = fmaf(c[mt][nt][h * 2 + 0], sv.x, bm + xv.x);
                ov.y = fmaf(c[mt][nt][h * 2 + 1], sv.y, bm + xv.y);
                *reinterpret_cast<float2*>(crow + nc) = ov;
            }
        }
    }
}

// ---------------- launcher ----------------
extern "C" void kernel_launch(void* const* d_in, const int* in_sizes, int n_in,
                              void* d_out, int out_size)
{
    const float* x      = (const float*)d_in[0];
    const float* gamma  = (const float*)d_in[1];
    const float* w_qkv  = (const float*)d_in[2];
    const float* b_qkv  = (const float*)d_in[3];
    const float* w_proj = (const float*)d_in[4];
    const float* b_proj = (const float*)d_in[5];
    float* out = (float*)d_out;

    __half *Wf, *xh;
    float *bias, *s;
    cudaGetSymbolAddress((void**)&Wf,   g_Wf);
    cudaGetSymbolAddress((void**)&xh,   g_xh);
    cudaGetSymbolAddress((void**)&bias, g_bias);
    cudaGetSymbolAddress((void**)&s,    g_s);

    cudaFuncSetAttribute(prep_all_kernel,
                         cudaFuncAttributeMaxDynamicSharedMemorySize, STAGE_B);
    cudaFuncSetAttribute(main_gemm_kernel,
                         cudaFuncAttributeMaxDynamicSharedMemorySize, SMEM_TOTAL);

    // blocks: 16 fw-gemm + 64 bias + 256 scale = 336
    prep_all_kernel<<<336, 256, STAGE_B>>>(x, gamma, w_qkv, b_qkv, w_proj, b_proj,
                                           Wf, bias, s, xh);

    dim3 grid(MDIM / BM, NDIM / BN);   // (4, 256): m fastest
    main_gemm_kernel<<<grid, 256, SMEM_TOTAL>>>(Wf, xh, s, bias, out);
}